// round 1
// baseline (speedup 1.0000x reference)
#include <cuda_runtime.h>

// Circuit_87634512707722 — batched 3-qubit statevector:
//   H(q0), H(q1), RX(theta0)(q0), RX(theta1)(q1), CNOT(ctrl=q0, tgt=q2)
// Fused: U_q = RX(theta_q) @ H = [[a-ib, a+ib],[a-ib, -(a+ib)]],
//   a = cos(theta/2)/sqrt2, b = sin(theta/2)/sqrt2.
// CNOT = permutation folded into the store (swap amps 4<->5, 6<->7).
//
// Memory: 128 B per element, B = 2^21 -> 256 MiB total. Pure HBM streaming.

#define BQ 2097152

__device__ __forceinline__ void pair_op(float a, float b,
                                        float& x0r, float& x0i,
                                        float& x1r, float& x1i) {
    // p = (a - i b) * x0 ; q = (a + i b) * x1 ; y0 = p+q ; y1 = p-q
    float pr = fmaf(a, x0r,  b * x0i);
    float pi = fmaf(a, x0i, -b * x0r);
    float qr = fmaf(a, x1r, -b * x1i);
    float qi = fmaf(a, x1i,  b * x1r);
    x0r = pr + qr;  x0i = pi + qi;
    x1r = pr - qr;  x1i = pi - qi;
}

__global__ __launch_bounds__(256)
void circuit_kernel(const float4* __restrict__ xr4,
                    const float4* __restrict__ xi4,
                    const float* __restrict__ theta,
                    float4* __restrict__ out4) {
    int b = blockIdx.x * blockDim.x + threadIdx.x;
    if (b >= BQ) return;

    // Front-batch all 4 global loads for MLP before any dependent math.
    float4 r0 = xr4[2 * b];
    float4 r1 = xr4[2 * b + 1];
    float4 i0 = xi4[2 * b];
    float4 i1 = xi4[2 * b + 1];

    // Gate constants (uniform across threads; cheap MUFU, hidden under LDG)
    float t0 = theta[0] * 0.5f;
    float t1 = theta[1] * 0.5f;
    const float inv_sqrt2 = 0.70710678118654752f;
    float s0, c0, s1, c1;
    __sincosf(t0, &s0, &c0);
    __sincosf(t1, &s1, &c1);
    float a0 = c0 * inv_sqrt2, b0 = s0 * inv_sqrt2;
    float a1 = c1 * inv_sqrt2, b1 = s1 * inv_sqrt2;

    float re[8] = {r0.x, r0.y, r0.z, r0.w, r1.x, r1.y, r1.z, r1.w};
    float im[8] = {i0.x, i0.y, i0.z, i0.w, i1.x, i1.y, i1.z, i1.w};

    // Qubit 0 (bit value 4): pairs (k, k+4)
#pragma unroll
    for (int k = 0; k < 4; k++)
        pair_op(a0, b0, re[k], im[k], re[k + 4], im[k + 4]);

    // Qubit 1 (bit value 2): pairs (k, k+2) for k in {0,1,4,5}
#pragma unroll
    for (int k = 0; k < 2; k++) {
        pair_op(a1, b1, re[k],     im[k],     re[k + 2], im[k + 2]);
        pair_op(a1, b1, re[k + 4], im[k + 4], re[k + 6], im[k + 6]);
    }

    // CNOT(ctrl=q0, tgt=q2): for control=1 half (indices 4..7), flip q2 (LSB):
    // out index 4+2*q1+q2 takes state 4+2*q1+(q2^1)  -> swap 4<->5, 6<->7.
    // Fold into interleaved (8,2) re/im store: 4 x float4, 64 B contiguous.
    out4[4 * b + 0] = make_float4(re[0], im[0], re[1], im[1]);
    out4[4 * b + 1] = make_float4(re[2], im[2], re[3], im[3]);
    out4[4 * b + 2] = make_float4(re[5], im[5], re[4], im[4]);
    out4[4 * b + 3] = make_float4(re[7], im[7], re[6], im[6]);
}

extern "C" void kernel_launch(void* const* d_in, const int* in_sizes, int n_in,
                              void* d_out, int out_size) {
    const float4* xr = (const float4*)d_in[0];
    const float4* xi = (const float4*)d_in[1];
    const float*  th = (const float*)d_in[2];
    // d_in[3] = angle, dead argument

    float4* out = (float4*)d_out;

    const int threads = 256;
    const int blocks = (BQ + threads - 1) / threads;
    circuit_kernel<<<blocks, threads>>>(xr, xi, th, out);
}

// round 2
// speedup vs baseline: 1.0942x; 1.0942x over previous
#include <cuda_runtime.h>

// Circuit_87634512707722 — batched 3-qubit statevector:
//   H(q0), H(q1), RX(theta0)(q0), RX(theta1)(q1), CNOT(ctrl=q0, tgt=q2)
// Fused per qubit: U_q = RX(theta_q)·H = [[a-ib, a+ib],[a-ib, -(a+ib)]],
//   a = cos(theta/2)/√2, b = sin(theta/2)/√2.
//
// Quarter-state lane mapping for perfect coalescing:
//   warp w covers 16 states. lane l owns amps {2(l&3), 2(l&3)+1} of
//   state (16w + (l>>2)) and state (16w + 8 + (l>>2)).
//   amp bit2 (q0) == lane bit1  -> exchange via shfl_xor(2)
//   amp bit1 (q1) == lane bit0  -> exchange via shfl_xor(1)
//   amp bit0 (q2) in-thread     -> CNOT = local swap when q0 half is 1
// All loads:  LDG.64  xr2[64w+l], xr2[64w+32+l] (contiguous 256B/warp)
// All stores: STG.128 out4[64w+l], out4[64w+32+l] (contiguous 512B/warp)

#define BQ 2097152
#define NTHREADS (2 * BQ)   // 2 threads per state (quarter-state each, 2 states/thread)

__device__ __forceinline__ void gate_round(float a, float bs, float sz, int xorm,
                                           float& x0r, float& x0i,
                                           float& x1r, float& x1i) {
    // z = (a - i*bs) * x  (bs carries the per-half sign; sz = combine sign)
    float z0r = fmaf(a, x0r,  bs * x0i);
    float z0i = fmaf(a, x0i, -bs * x0r);
    float z1r = fmaf(a, x1r,  bs * x1i);
    float z1i = fmaf(a, x1i, -bs * x1r);
    float w0r = __shfl_xor_sync(0xffffffffu, z0r, xorm);
    float w0i = __shfl_xor_sync(0xffffffffu, z0i, xorm);
    float w1r = __shfl_xor_sync(0xffffffffu, z1r, xorm);
    float w1i = __shfl_xor_sync(0xffffffffu, z1i, xorm);
    // half0: y = z + w ; half1: y = w - z
    x0r = fmaf(sz, z0r, w0r);
    x0i = fmaf(sz, z0i, w0i);
    x1r = fmaf(sz, z1r, w1r);
    x1i = fmaf(sz, z1i, w1i);
}

__global__ __launch_bounds__(256)
void circuit_kernel(const float2* __restrict__ xr2,
                    const float2* __restrict__ xi2,
                    const float* __restrict__ theta,
                    float4* __restrict__ out4) {
    int t = blockIdx.x * blockDim.x + threadIdx.x;
    int l = t & 31;
    int base = ((t >> 5) << 6) + l;   // float2-index for loads AND float4-index for stores

    // Front-batch all 4 coalesced loads (MLP=4)
    float2 ra  = xr2[base];
    float2 rb  = xr2[base + 32];
    float2 ia  = xi2[base];
    float2 ib_ = xi2[base + 32];

    // Gate constants (uniform; MUFU hidden under LDG latency)
    float t0 = theta[0] * 0.5f;
    float t1 = theta[1] * 0.5f;
    const float is2 = 0.70710678118654752f;
    float s0, c0, s1, c1;
    __sincosf(t0, &s0, &c0);
    __sincosf(t1, &s1, &c1);
    float a0 = c0 * is2, b0 = s0 * is2;
    float a1 = c1 * is2, b1 = s1 * is2;

    int h0 = (l >> 1) & 1;   // this lane's q0 bit value
    int h1 = l & 1;          // this lane's q1 bit value
    float bs0 = h0 ? -b0 : b0;
    float sz0 = h0 ? -1.0f : 1.0f;
    float bs1 = h1 ? -b1 : b1;
    float sz1 = h1 ? -1.0f : 1.0f;

    // State A amps: x0=(ra.x, ia.x), x1=(ra.y, ia.y); state B likewise.
    // Qubit 0 gate (partner lane l^2)
    gate_round(a0, bs0, sz0, 2, ra.x, ia.x,  ra.y, ia.y);
    gate_round(a0, bs0, sz0, 2, rb.x, ib_.x, rb.y, ib_.y);
    // Qubit 1 gate (partner lane l^1)
    gate_round(a1, bs1, sz1, 1, ra.x, ia.x,  ra.y, ia.y);
    gate_round(a1, bs1, sz1, 1, rb.x, ib_.x, rb.y, ib_.y);

    // CNOT(ctrl=q0, tgt=q2): lanes with q0==1 swap their local amp pair (bit0 flip)
    float A0r = h0 ? ra.y  : ra.x;
    float A0i = h0 ? ia.y  : ia.x;
    float A1r = h0 ? ra.x  : ra.y;
    float A1i = h0 ? ia.x  : ia.y;
    float B0r = h0 ? rb.y  : rb.x;
    float B0i = h0 ? ib_.y : ib_.x;
    float B1r = h0 ? rb.x  : rb.y;
    float B1i = h0 ? ib_.x : ib_.y;

    // Interleaved (re,im) output chunks, fully coalesced stores
    out4[base]      = make_float4(A0r, A0i, A1r, A1i);
    out4[base + 32] = make_float4(B0r, B0i, B1r, B1i);
}

extern "C" void kernel_launch(void* const* d_in, const int* in_sizes, int n_in,
                              void* d_out, int out_size) {
    const float2* xr = (const float2*)d_in[0];
    const float2* xi = (const float2*)d_in[1];
    const float*  th = (const float*)d_in[2];
    // d_in[3] = angle, dead argument

    float4* out = (float4*)d_out;

    const int threads = 256;
    const int blocks = NTHREADS / threads;   // 16384, exact
    circuit_kernel<<<blocks, threads>>>(xr, xi, th, out);
}